// round 15
// baseline (speedup 1.0000x reference)
#include <cuda_runtime.h>
#include <cstdint>

#define DIMC 1024
#define NH 16
#define HD 64
#define BB 4
#define TT 2048
#define BT (BB*TT)   // 8192

// Scratch (device globals: allocation-free contract)
__device__ float g_q[BT * DIMC];         // [B,H,T,D]
__device__ float g_k[BT * DIMC];
__device__ float g_v[BT * DIMC];
__device__ float g_y[BT * DIMC];         // attention out, [B,T,H,D] = [BT, C]
__device__ float g_rope[TT * 32 * 2];    // interleaved (cos, sin) per (t, j)

// ---------------------------------------------------------------------------
// TF32 helpers
// ---------------------------------------------------------------------------
__device__ __forceinline__ uint32_t f2tf32(float f) {
    uint32_t u;
    asm("cvt.rna.tf32.f32 %0, %1;" : "=r"(u) : "f"(f));
    return u;
}

__device__ __forceinline__ void mma_tf32(float c[4],
    uint32_t a0, uint32_t a1, uint32_t a2, uint32_t a3,
    uint32_t b0, uint32_t b1)
{
    asm volatile(
        "mma.sync.aligned.m16n8k8.row.col.f32.tf32.tf32.f32 "
        "{%0,%1,%2,%3}, {%4,%5,%6,%7}, {%8,%9}, {%0,%1,%2,%3};"
        : "+f"(c[0]), "+f"(c[1]), "+f"(c[2]), "+f"(c[3])
        : "r"(a0), "r"(a1), "r"(a2), "r"(a3), "r"(b0), "r"(b1));
}

// ---------------------------------------------------------------------------
// RoPE table init
// ---------------------------------------------------------------------------
__global__ void rope_init(float* R) {
    int i = blockIdx.x * 256 + threadIdx.x;      // TT*32 = 65536
    if (i >= TT * 32) return;
    int t = i >> 5, j = i & 31;
    float freq = __expf(-(float)j * 0.28782313662425575f);
    float s, c;
    sincosf((float)t * freq, &s, &c);
    R[i * 2]     = c;
    R[i * 2 + 1] = s;
}

// ---------------------------------------------------------------------------
// TF32 GEMM (unchanged from 806us version). MODE 1 = fused RoPE+split.
// ---------------------------------------------------------------------------
#define AST 20
#define BST 136
template<int MODE>
__global__ __launch_bounds__(128, 2) void gemm_tf32(
    const float* __restrict__ A, const float* __restrict__ Bm,
    float* __restrict__ C, int M, int N, int K,
    float* __restrict__ Qd, float* __restrict__ Kd, float* __restrict__ Vd,
    const float* __restrict__ Rope)
{
    __shared__ uint32_t As[2][128 * AST];   // [m][k]
    __shared__ uint32_t Bs[2][16 * BST];    // [k][n]

    const int tid  = threadIdx.x;
    const int lane = tid & 31;
    const int warp = tid >> 5;
    const int wm = warp & 1;
    const int wn = warp >> 1;
    const int m0 = blockIdx.y << 7;
    const int n0 = blockIdx.x << 7;
    const int m0w = wm * 64;
    const int n0w = wn * 64;

    const int row = lane >> 2;
    const int tig = lane & 3;

    int raA[4], caA[4], rbB[4], cbB[4];
    #pragma unroll
    for (int i = 0; i < 4; i++) {
        int idx = tid + i * 128;
        raA[i] = idx >> 2;  caA[i] = (idx & 3) << 2;
        rbB[i] = idx >> 5;  cbB[i] = (idx & 31) << 2;
    }

    float acc[4][8][4];
    #pragma unroll
    for (int i = 0; i < 4; i++)
        #pragma unroll
        for (int j = 0; j < 8; j++)
            #pragma unroll
            for (int r = 0; r < 4; r++) acc[i][j][r] = 0.0f;

    const int KT = K >> 4;

    float4 av[4], bv[4];
    #pragma unroll
    for (int i = 0; i < 4; i++) {
        av[i] = *(const float4*)&A[(size_t)(m0 + raA[i]) * K + caA[i]];
        bv[i] = *(const float4*)&Bm[(size_t)rbB[i] * N + n0 + cbB[i]];
    }
    #pragma unroll
    for (int i = 0; i < 4; i++) {
        uint4 u;
        u.x = f2tf32(av[i].x); u.y = f2tf32(av[i].y);
        u.z = f2tf32(av[i].z); u.w = f2tf32(av[i].w);
        *(uint4*)&As[0][raA[i] * AST + caA[i]] = u;
        u.x = f2tf32(bv[i].x); u.y = f2tf32(bv[i].y);
        u.z = f2tf32(bv[i].z); u.w = f2tf32(bv[i].w);
        *(uint4*)&Bs[0][rbB[i] * BST + cbB[i]] = u;
    }
    __syncthreads();

    for (int ki = 0; ki < KT; ki++) {
        const int cur = ki & 1;
        const int nxt = cur ^ 1;
        const bool more = (ki + 1) < KT;

        if (more) {
            int k0 = (ki + 1) << 4;
            #pragma unroll
            for (int i = 0; i < 4; i++) {
                av[i] = *(const float4*)&A[(size_t)(m0 + raA[i]) * K + k0 + caA[i]];
                bv[i] = *(const float4*)&Bm[(size_t)(k0 + rbB[i]) * N + n0 + cbB[i]];
            }
        }

        const uint32_t* Ac = &As[cur][0];
        const uint32_t* Bc = &Bs[cur][0];
        #pragma unroll
        for (int kc = 0; kc < 16; kc += 8) {
            uint32_t af[4][4], bf[8][2];
            #pragma unroll
            for (int mt = 0; mt < 4; mt++) {
                int mr = m0w + mt * 16 + row;
                af[mt][0] = Ac[mr * AST + kc + tig];
                af[mt][1] = Ac[(mr + 8) * AST + kc + tig];
                af[mt][2] = Ac[mr * AST + kc + tig + 4];
                af[mt][3] = Ac[(mr + 8) * AST + kc + tig + 4];
            }
            #pragma unroll
            for (int nt = 0; nt < 8; nt++) {
                int nc = n0w + nt * 8 + row;
                bf[nt][0] = Bc[(kc + tig) * BST + nc];
                bf[nt][1] = Bc[(kc + tig + 4) * BST + nc];
            }
            #pragma unroll
            for (int mt = 0; mt < 4; mt++)
                #pragma unroll
                for (int nt = 0; nt < 8; nt++)
                    mma_tf32(acc[mt][nt], af[mt][0], af[mt][1], af[mt][2], af[mt][3],
                             bf[nt][0], bf[nt][1]);
        }

        if (more) {
            #pragma unroll
            for (int i = 0; i < 4; i++) {
                uint4 u;
                u.x = f2tf32(av[i].x); u.y = f2tf32(av[i].y);
                u.z = f2tf32(av[i].z); u.w = f2tf32(av[i].w);
                *(uint4*)&As[nxt][raA[i] * AST + caA[i]] = u;
                u.x = f2tf32(bv[i].x); u.y = f2tf32(bv[i].y);
                u.z = f2tf32(bv[i].z); u.w = f2tf32(bv[i].w);
                *(uint4*)&Bs[nxt][rbB[i] * BST + cbB[i]] = u;
            }
        }
        __syncthreads();
    }

    if (MODE == 0) {
        #pragma unroll
        for (int mt = 0; mt < 4; mt++) {
            int mr = m0 + m0w + mt * 16 + row;
            #pragma unroll
            for (int nt = 0; nt < 8; nt++) {
                int nc = n0 + n0w + nt * 8 + 2 * tig;
                float2 lo = { acc[mt][nt][0], acc[mt][nt][1] };
                float2 hi = { acc[mt][nt][2], acc[mt][nt][3] };
                *(float2*)&C[(size_t)mr * N + nc] = lo;
                *(float2*)&C[(size_t)(mr + 8) * N + nc] = hi;
            }
        }
    } else {
        const int seg  = n0 >> 10;                       // 0=q, 1=k, 2=v
        const int head = ((n0 & 1023) + n0w) >> 6;
        float* dst = (seg == 0) ? Qd : (seg == 1) ? Kd : Vd;
        const float scale = (seg == 0) ? 0.125f : 1.0f;

        #pragma unroll
        for (int mt = 0; mt < 4; mt++) {
            #pragma unroll
            for (int half = 0; half < 2; half++) {
                const int bt = m0 + m0w + mt * 16 + row + half * 8;
                const int t = bt & (TT - 1);
                const int b = bt >> 11;
                const size_t base = ((size_t)(b * NH + head) * TT + t) * HD;
                if (seg == 2) {
                    #pragma unroll
                    for (int nt = 0; nt < 8; nt++) {
                        float2 o = { acc[mt][nt][half * 2], acc[mt][nt][half * 2 + 1] };
                        *(float2*)&dst[base + nt * 8 + 2 * tig] = o;
                    }
                } else {
                    float4 tb[4];
                    #pragma unroll
                    for (int q = 0; q < 4; q++)
                        tb[q] = *(const float4*)&Rope[(t * 32 + q * 8 + 2 * tig) * 2];
                    #pragma unroll
                    for (int nt = 0; nt < 8; nt++) {
                        const int q = nt & 3;
                        const float sg = (nt < 4) ? -1.0f : 1.0f;
                        float v0 = acc[mt][nt][half * 2];
                        float v1 = acc[mt][nt][half * 2 + 1];
                        float p0 = acc[mt][nt ^ 4][half * 2];
                        float p1 = acc[mt][nt ^ 4][half * 2 + 1];
                        float2 o = { (v0 * tb[q].x + sg * p0 * tb[q].y) * scale,
                                     (v1 * tb[q].z + sg * p1 * tb[q].w) * scale };
                        *(float2*)&dst[base + nt * 8 + 2 * tig] = o;
                    }
                }
            }
        }
    }
}

// ---------------------------------------------------------------------------
// Tensor-core flash attention (causal). 64x64 tiles, 128 threads (4 warps).
// NEW: K/V register prefetch — next tile's LDGs issue before the compute of
// the current tile, hiding global latency. cvt at STS time (numerics equal).
// ---------------------------------------------------------------------------
#define KST 68
#define VST 72
#define PST 72
__global__ __launch_bounds__(128) void attn_tc(
    const float* __restrict__ Q, const float* __restrict__ K,
    const float* __restrict__ V, float* __restrict__ Y)
{
    extern __shared__ uint32_t smw[];
    uint32_t* Ks = smw;                // [kseq][d]  64 x KST
    uint32_t* Vs = Ks + 64 * KST;      // [kseq][d]  64 x VST
    uint32_t* Ps = Vs + 64 * VST;      // [q][kseq]  64 x PST

    const int tid  = threadIdx.x;
    const int lane = tid & 31;
    const int warp = tid >> 5;         // 0..3
    const int row  = lane >> 2;        // 0..7
    const int tig  = lane & 3;         // 0..3
    const int qb = blockIdx.x;
    const int bh = blockIdx.y;
    const int b  = bh >> 4;
    const int h  = bh & 15;
    const int r0 = warp * 16 + row;    // owned rows r0, r0+8

    const float* Qg = Q + ((size_t)bh * TT + qb * 64) * HD;
    const float* Kg = K + (size_t)bh * TT * HD;
    const float* Vg = V + (size_t)bh * TT * HD;

    uint32_t qh[8][4];
    #pragma unroll
    for (int s = 0; s < 8; s++) {
        qh[s][0] = f2tf32(Qg[r0 * 64 + 8 * s + tig]);
        qh[s][1] = f2tf32(Qg[(r0 + 8) * 64 + 8 * s + tig]);
        qh[s][2] = f2tf32(Qg[r0 * 64 + 8 * s + tig + 4]);
        qh[s][3] = f2tf32(Qg[(r0 + 8) * 64 + 8 * s + tig + 4]);
    }

    float m_[2] = { -1e30f, -1e30f };
    float l_[2] = { 0.0f, 0.0f };
    float oacc[8][4];
    #pragma unroll
    for (int nt = 0; nt < 8; nt++)
        #pragma unroll
        for (int r = 0; r < 4; r++) oacc[nt][r] = 0.0f;

    // per-thread staging coordinates (8 float4 positions per tile per array)
    const int kRow = tid >> 4;               // base row (stride 8 via it*8? no:)
    // idx = tid + it*128 -> k = idx>>4 = (tid>>4) + it*8 ; d0 = (tid&15)*4
    const int d0 = (tid & 15) << 2;

    // prologue: prefetch kb=0 K/V into registers
    float4 kvr[8], vvr[8];
    #pragma unroll
    for (int it = 0; it < 8; it++) {
        int k = kRow + it * 8;
        kvr[it] = *(const float4*)&Kg[(size_t)k * 64 + d0];
        vvr[it] = *(const float4*)&Vg[(size_t)k * 64 + d0];
    }

    for (int kb = 0; kb <= qb; kb++) {
        __syncthreads();   // all warps done reading Ks/Vs from previous iter
        // store prefetched tile (cvt at store: same per-element rounding)
        #pragma unroll
        for (int it = 0; it < 8; it++) {
            int k = kRow + it * 8;
            uint4 ku = { f2tf32(kvr[it].x), f2tf32(kvr[it].y),
                         f2tf32(kvr[it].z), f2tf32(kvr[it].w) };
            uint4 vu = { f2tf32(vvr[it].x), f2tf32(vvr[it].y),
                         f2tf32(vvr[it].z), f2tf32(vvr[it].w) };
            *(uint4*)&Ks[k * KST + d0] = ku;
            *(uint4*)&Vs[k * VST + d0] = vu;
        }
        __syncthreads();

        // prefetch NEXT tile (latency overlapped with the MMAs below)
        if (kb < qb) {
            #pragma unroll
            for (int it = 0; it < 8; it++) {
                int k = (kb + 1) * 64 + kRow + it * 8;
                kvr[it] = *(const float4*)&Kg[(size_t)k * 64 + d0];
                vvr[it] = *(const float4*)&Vg[(size_t)k * 64 + d0];
            }
        }

        float sacc[8][4];
        #pragma unroll
        for (int nt = 0; nt < 8; nt++)
            #pragma unroll
            for (int r = 0; r < 4; r++) sacc[nt][r] = 0.0f;

        #pragma unroll
        for (int s = 0; s < 8; s++) {
            int kc = 8 * s;
            #pragma unroll
            for (int nt = 0; nt < 8; nt++) {
                int nc = nt * 8 + row;
                uint32_t b0 = Ks[nc * KST + kc + tig];
                uint32_t b1 = Ks[nc * KST + kc + tig + 4];
                mma_tf32(sacc[nt], qh[s][0], qh[s][1], qh[s][2], qh[s][3], b0, b1);
            }
        }

        if (kb == qb) {
            #pragma unroll
            for (int nt = 0; nt < 8; nt++)
                #pragma unroll
                for (int r = 0; r < 4; r++) {
                    int ql = r0 + 8 * (r >> 1);
                    int kl = nt * 8 + 2 * tig + (r & 1);
                    if (kl > ql) sacc[nt][r] = -1e30f;
                }
        }

        #pragma unroll
        for (int hh = 0; hh < 2; hh++) {
            float mx = -1e30f;
            #pragma unroll
            for (int nt = 0; nt < 8; nt++)
                mx = fmaxf(mx, fmaxf(sacc[nt][2 * hh], sacc[nt][2 * hh + 1]));
            mx = fmaxf(mx, __shfl_xor_sync(0xffffffffu, mx, 1));
            mx = fmaxf(mx, __shfl_xor_sync(0xffffffffu, mx, 2));
            float mnew = fmaxf(m_[hh], mx);
            float alpha = __expf(m_[hh] - mnew);
            m_[hh] = mnew;
            float rs = 0.0f;
            int qrow = r0 + 8 * hh;
            #pragma unroll
            for (int nt = 0; nt < 8; nt++) {
                float p0 = __expf(sacc[nt][2 * hh] - mnew);
                float p1 = __expf(sacc[nt][2 * hh + 1] - mnew);
                rs += p0 + p1;
                uint2 pu = { f2tf32(p0), f2tf32(p1) };
                *(uint2*)&Ps[qrow * PST + nt * 8 + 2 * tig] = pu;
                oacc[nt][2 * hh]     *= alpha;
                oacc[nt][2 * hh + 1] *= alpha;
            }
            rs += __shfl_xor_sync(0xffffffffu, rs, 1);
            rs += __shfl_xor_sync(0xffffffffu, rs, 2);
            l_[hh] = l_[hh] * alpha + rs;
        }
        __syncwarp();

        #pragma unroll
        for (int s = 0; s < 8; s++) {
            int kc = 8 * s;
            uint32_t a0 = Ps[r0 * PST + kc + tig];
            uint32_t a1 = Ps[(r0 + 8) * PST + kc + tig];
            uint32_t a2 = Ps[r0 * PST + kc + tig + 4];
            uint32_t a3 = Ps[(r0 + 8) * PST + kc + tig + 4];
            #pragma unroll
            for (int nt = 0; nt < 8; nt++) {
                int nc = nt * 8 + row;
                uint32_t b0 = Vs[(kc + tig) * VST + nc];
                uint32_t b1 = Vs[(kc + tig + 4) * VST + nc];
                mma_tf32(oacc[nt], a0, a1, a2, a3, b0, b1);
            }
        }
    }

    #pragma unroll
    for (int hh = 0; hh < 2; hh++) {
        float inv = 1.0f / l_[hh];
        int qg = qb * 64 + r0 + 8 * hh;
        size_t base = ((size_t)(b * TT + qg) * NH + h) * HD;
        #pragma unroll
        for (int nt = 0; nt < 8; nt++) {
            int d = nt * 8 + 2 * tig;
            float2 o2 = { oacc[nt][2 * hh] * inv, oacc[nt][2 * hh + 1] * inv };
            *(float2*)&Y[base + d] = o2;
        }
    }
}

// ---------------------------------------------------------------------------
extern "C" void kernel_launch(void* const* d_in, const int* in_sizes, int n_in,
                              void* d_out, int out_size)
{
    const float* x     = (const float*)d_in[0];   // [B,T,C]
    const float* Wqkv  = (const float*)d_in[1];   // [C, 3C]
    const float* Wproj = (const float*)d_in[2];   // [C, C]
    float* out = (float*)d_out;                   // [B,T,C]

    float *q, *k, *v, *y, *rope;
    cudaGetSymbolAddress((void**)&q,    g_q);
    cudaGetSymbolAddress((void**)&k,    g_k);
    cudaGetSymbolAddress((void**)&v,    g_v);
    cudaGetSymbolAddress((void**)&y,    g_y);
    cudaGetSymbolAddress((void**)&rope, g_rope);

    // 0) RoPE cos/sin table
    rope_init<<<(TT * 32 + 255) / 256, 256>>>(rope);

    // 1) qkv = x @ Wqkv with fused RoPE + head-split epilogue
    gemm_tf32<1><<<dim3(3 * DIMC / 128, BT / 128), 128>>>(
        x, Wqkv, nullptr, BT, 3 * DIMC, DIMC, q, k, v, rope);

    // 2) causal flash attention (tensor cores, K/V register prefetch)
    const int smem_bytes = 64 * (KST + VST + PST) * (int)sizeof(uint32_t);  // 54272
    cudaFuncSetAttribute(attn_tc, cudaFuncAttributeMaxDynamicSharedMemorySize, smem_bytes);
    attn_tc<<<dim3(TT / 64, BB * NH), 128, smem_bytes>>>(q, k, v, y);

    // 3) out = y @ Wproj  (8192 x 1024 x 1024)
    gemm_tf32<0><<<dim3(DIMC / 128, BT / 128), 128>>>(
        y, Wproj, out, BT, DIMC, DIMC, nullptr, nullptr, nullptr, nullptr);
}